// round 7
// baseline (speedup 1.0000x reference)
#include <cuda_runtime.h>
#include <cuda_bf16.h>
#include <math_constants.h>

// Fused greedy CTC decode:
//   index[t] = argmax_v emission[t, v]  (first occurrence on ties)
//   char[t]  = -1 if index==0 ; index-1 if index>1 ; 0 if index==1
//   keep[t]  = (char[t] != char[t-1]) && (char[t] != -1)   (char[-1] := -2)
// Output (float32): [0..T) = (float)index, [T..2T) = keep (0.0/1.0).
//
// 8 warps x 4 rows = 32 rows/block, grid 2048. Lane-local argmax via a
// chained compare (registers recycled as loads are consumed -> ~30 regs),
// warp reduce via 2x REDUX (max on monotone key, min on index).
// __launch_bounds__(256, 8) pins regs <= 32 for full occupancy.
// Epilogue stores are staged in smem and written coalesced.

static constexpr int V = 512;
static constexpr int WARPS = 8;
static constexpr int R = 4;                         // rows per warp
static constexpr int ROWS_PER_BLOCK = WARPS * R;    // 32

// Strictly monotone float -> uint map (order- and equality-preserving).
__device__ __forceinline__ unsigned mono(float f)
{
    unsigned u = __float_as_uint(f);
    return u ^ ((unsigned)((int)u >> 31) | 0x80000000u);
}

__device__ __forceinline__ void cmp4(const float4 v, int e, float& best, int& bidx)
{
    if (v.x > best) { best = v.x; bidx = e;     }
    if (v.y > best) { best = v.y; bidx = e + 1; }
    if (v.z > best) { best = v.z; bidx = e + 2; }
    if (v.w > best) { best = v.w; bidx = e + 3; }
}

// Warp argmax of one row; returns first-occurrence argmax (uniform).
__device__ __forceinline__ int warp_argmax_row(const float* __restrict__ em,
                                               int row, int lane)
{
    const float4* __restrict__ p =
        reinterpret_cast<const float4*>(em + (size_t)row * V);

    // Front-batched loads; consumed in order so registers recycle.
    float best = -CUDART_INF_F;
    int   bidx = 0;
#pragma unroll
    for (int c = 0; c < 4; ++c)
        cmp4(p[lane + c * 32], lane * 4 + c * 128, best, bidx);

    // Warp reduce: REDUX max on monotone key, REDUX min for first index.
    const unsigned k = mono(best);
    const unsigned m = __reduce_max_sync(0xFFFFFFFFu, k);
    const unsigned cand = (k == m) ? (unsigned)bidx : 0x7FFFFFFFu;
    return (int)__reduce_min_sync(0xFFFFFFFFu, cand);
}

__device__ __forceinline__ int ctc_char(int i)
{
    return (i == 0) ? -1 : ((i > 1) ? i - 1 : 0);
}

__global__ __launch_bounds__(WARPS * 32, 8)
void ctc_fused_kernel(const float* __restrict__ em,
                      float* __restrict__ out_index,
                      float* __restrict__ out_keep,
                      int T)
{
    __shared__ int idx_s[ROWS_PER_BLOCK];
    __shared__ int ch[ROWS_PER_BLOCK + 1];   // ch[0] = char of row base-1

    const int warp = threadIdx.x >> 5;
    const int lane = threadIdx.x & 31;
    const int base = blockIdx.x * ROWS_PER_BLOCK;

#pragma unroll
    for (int j = 0; j < R; ++j) {
        const int local = warp * R + j;
        const int bidx  = warp_argmax_row(em, base + local, lane);
        if (lane == 0) {
            idx_s[local]  = bidx;
            ch[1 + local] = ctc_char(bidx);
        }
    }

    // Last warp resolves the block-boundary predecessor row.
    if (warp == WARPS - 1) {
        if (base == 0) {
            if (lane == 0) ch[0] = -2;           // char[-1] sentinel
        } else {
            const int bi = warp_argmax_row(em, base - 1, lane);
            if (lane == 0) ch[0] = ctc_char(bi);
        }
    }
    __syncthreads();

    // Coalesced epilogue: warp 0 writes index, warp 1 writes keep.
    if (threadIdx.x < ROWS_PER_BLOCK) {
        out_index[base + threadIdx.x] = (float)idx_s[threadIdx.x];
    } else if (threadIdx.x < 2 * ROWS_PER_BLOCK) {
        const int l = threadIdx.x - ROWS_PER_BLOCK;
        const int c  = ch[l + 1];
        const int pc = ch[l];
        out_keep[base + l] = (c != pc && c != -1) ? 1.0f : 0.0f;
    }
}

extern "C" void kernel_launch(void* const* d_in, const int* in_sizes, int n_in,
                              void* d_out, int out_size)
{
    const float* em = (const float*)d_in[0];
    const int T = in_sizes[0] / V;           // 65536 (divisible by 32)

    float* out       = (float*)d_out;
    float* out_index = out;
    float* out_keep  = out + T;

    const int grid = T / ROWS_PER_BLOCK;     // 2048
    ctc_fused_kernel<<<grid, WARPS * 32>>>(em, out_index, out_keep, T);
}